// round 5
// baseline (speedup 1.0000x reference)
#include <cuda_runtime.h>

// Windowed local attention, k=7, H=W=256, C=32, fp32.
// 256 thr / 32x4 tile, 2 threads per pixel (16ch each, shfl-combined).
// Smem layout [c/4][pos][c%4]: LDS.128 loads 4 channels; fma.rn.f32x2 packs
// 2 MACs/instr. p-outer loop keeps one score accumulator live at a time.

#define H_IMG 256
#define W_IMG 256
#define C 32
#define HC 16              // channels per thread
#define K 7
#define PAD 3
#define TX 32
#define TY 4
#define HW 38
#define HH 10
#define CS 381             // positions stride (380 used, +1 pad)
#define CS4 (CS * 4)       // floats per 4-channel group
#define NTHREADS 256
#define SMEM_BYTES (8 * CS4 * 4)   // 8 groups of 4 channels

typedef unsigned long long u64;

__device__ __forceinline__ u64 pack2(float lo, float hi) {
    u64 r;
    asm("mov.b64 %0, {%1, %2};" : "=l"(r) : "f"(lo), "f"(hi));
    return r;
}
__device__ __forceinline__ float lo2(u64 v) {
    float a, b;
    asm("mov.b64 {%0, %1}, %2;" : "=f"(a), "=f"(b) : "l"(v));
    return a;
}
__device__ __forceinline__ float hi2(u64 v) {
    float a, b;
    asm("mov.b64 {%0, %1}, %2;" : "=f"(a), "=f"(b) : "l"(v));
    return b;
}
__device__ __forceinline__ void ffma2(u64& d, u64 a, u64 b) {
    asm("fma.rn.f32x2 %0, %1, %2, %0;" : "+l"(d) : "l"(a), "l"(b));
}

// Stage all 32 channels of src halo: [g][pos][j] layout, float4 per store.
__device__ __forceinline__ void stage_halo(float* __restrict__ buf,
                                           const float* __restrict__ src,
                                           int bx, int by, int tid) {
    for (int idx = tid; idx < HW * HH * 8; idx += NTHREADS) {
        int g  = idx & 7;
        int s  = idx >> 3;
        int wp = s % HW;
        int hp = s / HW;
        int gw = bx * TX - PAD + wp;
        int gh = by * TY - PAD + hp;
        float4 r = make_float4(0.f, 0.f, 0.f, 0.f);
        if (gw >= 0 && gw < W_IMG && gh >= 0 && gh < H_IMG) {
            r = *reinterpret_cast<const float4*>(src + ((gh << 8) + gw) * C + (g << 2));
        }
        *reinterpret_cast<float4*>(buf + g * CS4 + s * 4) = r;
    }
}

__global__ __launch_bounds__(NTHREADS, 3)
void local_attn_kernel(const float* __restrict__ main_in,
                       const float* __restrict__ ref_in,
                       const float* __restrict__ val_in,
                       float* __restrict__ out) {
    extern __shared__ float smem[];
    float* buf = smem;

    const int tid = threadIdx.x;
    const int bx = blockIdx.x, by = blockIdx.y;
    const int wid = tid >> 5;
    const int lane = tid & 31;
    const int py = wid >> 1;
    const int px = ((wid & 1) << 4) + (lane & 15);
    const int half = lane >> 4;              // channel half 0/1
    const int gb = half << 2;                // first 4-ch group: 0 or 4

    const int gpix = (((by * TY + py) << 8) + bx * TX + px) * C;
    const int s0 = py * HW + px;

    // ---- Stage ref halo ----
    stage_halo(buf, ref_in, bx, by, tid);

    // ---- Query: this thread's 16 channels as 8 packed pairs ----
    u64 m2[8];
    #pragma unroll
    for (int i = 0; i < 4; i++) {
        float4 t = *reinterpret_cast<const float4*>(main_in + gpix + (gb << 2) + 4 * i);
        m2[2 * i + 0] = pack2(t.x, t.y);
        m2[2 * i + 1] = pack2(t.z, t.w);
    }

    __syncthreads();

    // ---- Pass 1: scores (p-outer, 4x LDS.128 + 8x FFMA2 per p) ----
    float sc[K * K];
    const float* rb = buf + gb * CS4;
    #pragma unroll
    for (int dh = 0; dh < K; dh++) {
        #pragma unroll
        for (int dw = 0; dw < K; dw++) {
            int s = (s0 + dh * HW + dw) * 4;
            u64 a0 = pack2(0.f, 0.f), a1 = pack2(0.f, 0.f);
            #pragma unroll
            for (int gr = 0; gr < 4; gr++) {
                float4 r = *reinterpret_cast<const float4*>(rb + gr * CS4 + s);
                ffma2(a0, pack2(r.x, r.y), m2[2 * gr + 0]);
                ffma2(a1, pack2(r.z, r.w), m2[2 * gr + 1]);
            }
            float part = lo2(a0) + hi2(a0) + lo2(a1) + hi2(a1);
            // combine the two channel-halves of this pixel
            sc[dh * K + dw] = part + __shfl_xor_sync(0xffffffffu, part, 16);
        }
    }

    // ---- Softmax over 49 (OOB positions carry score 0, included) ----
    float mx = sc[0];
    #pragma unroll
    for (int p = 1; p < K * K; p++) mx = fmaxf(mx, sc[p]);
    float sum = 0.f;
    #pragma unroll
    for (int p = 0; p < K * K; p++) {
        sc[p] = __expf(sc[p] - mx);
        sum += sc[p];
    }
    float inv = 1.f / sum;
    #pragma unroll
    for (int p = 0; p < K * K; p++) sc[p] *= inv;

    // ---- Stage val halo ----
    __syncthreads();
    stage_halo(buf, val_in, bx, by, tid);
    __syncthreads();

    // ---- Pass 2: 16 output channels as 8 packed accumulators ----
    u64 acc[8];
    #pragma unroll
    for (int j = 0; j < 8; j++) acc[j] = pack2(0.f, 0.f);

    const float* vb = buf + gb * CS4;
    #pragma unroll
    for (int dh = 0; dh < K; dh++) {
        #pragma unroll
        for (int dw = 0; dw < K; dw++) {
            int s = (s0 + dh * HW + dw) * 4;
            float w = sc[dh * K + dw];
            u64 w2 = pack2(w, w);
            #pragma unroll
            for (int gr = 0; gr < 4; gr++) {
                float4 v = *reinterpret_cast<const float4*>(vb + gr * CS4 + s);
                ffma2(acc[2 * gr + 0], pack2(v.x, v.y), w2);
                ffma2(acc[2 * gr + 1], pack2(v.z, v.w), w2);
            }
        }
    }

    float* o = out + gpix + (gb << 2);
    #pragma unroll
    for (int i = 0; i < 4; i++) {
        *reinterpret_cast<float4*>(o + 4 * i) =
            make_float4(lo2(acc[2 * i]), hi2(acc[2 * i]),
                        lo2(acc[2 * i + 1]), hi2(acc[2 * i + 1]));
    }
}

extern "C" void kernel_launch(void* const* d_in, const int* in_sizes, int n_in,
                              void* d_out, int out_size) {
    const float* main_in = (const float*)d_in[0];
    const float* ref_in  = (const float*)d_in[1];
    const float* val_in  = (const float*)d_in[2];
    float* out = (float*)d_out;

    cudaFuncSetAttribute(local_attn_kernel,
                         cudaFuncAttributeMaxDynamicSharedMemorySize, SMEM_BYTES);

    dim3 grid(W_IMG / TX, H_IMG / TY);
    local_attn_kernel<<<grid, NTHREADS, SMEM_BYTES>>>(main_in, ref_in, val_in, out);
}